// round 12
// baseline (speedup 1.0000x reference)
#include <cuda_runtime.h>
#include <cstdint>

// CRF forward (logZ) + Viterbi merged into ONE warp per batch.
// R11 with ONE fix: #pragma unroll 8 so the depth-8 prefetch ring index
// (s&7) is compile-time-constant per unrolled copy -> fq[] stays in
// REGISTERS (R11's unroll-4 made j dynamic -> local-memory spill -> 574us).
// Forward: exp-domain ratio renorm, exact power-of-2 scaling (no rcp/log on
// chain). Viterbi: exact fmax tree + first-index eq-bitmap argmax.
// out (f32): [0,B) logZ, [B,2B) best_score, [2B, 2B+S*B*T) pointers.

constexpr int S = 1024, B = 1024, T = 32;
#define NEG_INF   (-10000.0f)
#define START_TAG 29
#define STOP_TAG  30

__device__ __forceinline__ void ffma2(unsigned long long& d, unsigned long long a, unsigned long long b) {
    asm("fma.rn.f32x2 %0, %1, %2, %0;" : "+l"(d) : "l"(a), "l"(b));
}
__device__ __forceinline__ unsigned long long fadd2(unsigned long long a, unsigned long long b) {
    unsigned long long r;
    asm("add.rn.f32x2 %0, %1, %2;" : "=l"(r) : "l"(a), "l"(b));
    return r;
}
__device__ __forceinline__ unsigned long long pack2(float lo, float hi) {
    unsigned long long r;
    asm("mov.b64 %0, {%1, %2};" : "=l"(r) : "f"(lo), "f"(hi));
    return r;
}
__device__ __forceinline__ void unpack2(unsigned long long v, float& lo, float& hi) {
    asm("mov.b64 {%0, %1}, %2;" : "=f"(lo), "=f"(hi) : "l"(v));
}

__global__ void __launch_bounds__(32) crf_kernel(
    const float* __restrict__ feats, const float* __restrict__ mask,
    const float* __restrict__ trans, float* __restrict__ out)
{
    __shared__ __align__(16) float Eb[2][T];   // forward exp-state broadcast
    __shared__ __align__(16) float Sb[2][T];   // viterbi score broadcast

    const int lane = threadIdx.x;
    const int b    = blockIdx.x;

    // length = first s with mask[s][b]==0 (mask monotone). One-time search.
    int lo = 0, hi = S;
    #pragma unroll 1
    while (lo < hi) {
        const int mid = (lo + hi) >> 1;
        if (__ldg(mask + (size_t)mid * B + b) != 0.0f) lo = mid + 1; else hi = mid;
    }
    const int len = lo;

    const float L2E = 1.4426950408889634f;
    const float LN2 = 0.6931471805599453f;

    // Per-lane transition row (lane = target tag i). W = exp(t) for forward
    // (forbidden -1e4 entries underflow to exactly 0 == contributing -inf).
    unsigned long long W2[T / 2];
    float tr[T];
    #pragma unroll
    for (int k = 0; k < T / 2; k++) {
        const float t0 = __ldg(trans + lane * T + 2 * k);
        const float t1 = __ldg(trans + lane * T + 2 * k + 1);
        tr[2 * k] = t0; tr[2 * k + 1] = t1;
        W2[k] = pack2(__expf(t0), __expf(t1));
    }
    const float tstop = __ldg(trans + STOP_TAG * T + lane);

    // State: alpha = log(E) + O.
    float Ev = (lane == START_TAG) ? 1.0f : 0.0f;   // exp(alpha0 - 0)
    float sc = (lane == START_TAG) ? 0.0f : NEG_INF;
    float O  = 0.0f;

    Eb[0][lane] = Ev;
    Sb[0][lane] = sc;
    __syncwarp();

    const size_t BT = (size_t)B * T;
    const float* fp = feats + (size_t)b * T + lane;

    // Depth-8 prefetch ring (register-resident under unroll 8).
    float fq[8];
    #pragma unroll
    for (int k = 0; k < 8; k++) fq[k] = __ldg(fp + (size_t)k * BT);
    const float* pf = fp + 8 * BT;
    int rem = S - 1 - 8;                 // prefetch rows remaining before clamp

    float* pout = out + 2 * B + (size_t)b * T + lane;

    #pragma unroll 8
    for (int s = 0; s < len; s++) {
        const int j  = s & 7;                       // constant per unrolled copy
        const int pb = s & 1;
        const float fv = fq[j];
        fq[j] = __ldg(pf);                          // row s+8 (clamped at S-1)
        if (rem > 0) { pf += BT; rem--; }

        // Off-chain: X_i = exp(feat_i - feat_0), bounded args.
        const float fv0 = __shfl_sync(0xffffffffu, fv, 0);
        float X;
        asm("ex2.approx.ftz.f32 %0, %1;" : "=f"(X) : "f"((fv - fv0) * L2E));

        // ---------- Viterbi chain ----------
        const float4* s4 = (const float4*)Sb[pb];
        float vv[T];
        #pragma unroll
        for (int k = 0; k < 8; k++) {
            const float4 q = s4[k];
            vv[4 * k]     = q.x + tr[4 * k];
            vv[4 * k + 1] = q.y + tr[4 * k + 1];
            vv[4 * k + 2] = q.z + tr[4 * k + 2];
            vv[4 * k + 3] = q.w + tr[4 * k + 3];
        }
        float mx[16];
        #pragma unroll
        for (int i = 0; i < 16; i++) mx[i] = fmaxf(vv[i], vv[i + 16]);
        #pragma unroll
        for (int off = 8; off; off >>= 1)
            #pragma unroll
            for (int i = 0; i < 8; i++)
                if (i < off) mx[i] = fmaxf(mx[i], mx[i + off]);
        const float vmax = mx[0];
        sc = vmax + fv;                             // exact update

        // ---------- Forward chain (no log/rcp) ----------
        const ulonglong2* e2 = (const ulonglong2*)Eb[pb];
        unsigned long long a0 = 0ull, a1 = 0ull, a2 = 0ull, a3 = 0ull;
        #pragma unroll
        for (int k = 0; k < 4; k++) {
            const ulonglong2 qa = e2[2 * k];
            const ulonglong2 qb = e2[2 * k + 1];
            ffma2(a0, qa.x, W2[4 * k]);
            ffma2(a1, qa.y, W2[4 * k + 1]);
            ffma2(a2, qb.x, W2[4 * k + 2]);
            ffma2(a3, qb.y, W2[4 * k + 3]);
        }
        const unsigned long long sAB = fadd2(fadd2(a0, a1), fadd2(a2, a3));
        float sl, sh; unpack2(sAB, sl, sh);
        const float sum = sl + sh;                  // sum_0 > 0 always

        // Power-of-2 renorm: e = exponent(sum_0); E' = sum * 2^-e * X. Stable.
        const int s0b = __shfl_sync(0xffffffffu, __float_as_int(sum), 0);
        const int e   = (s0b >> 23) - 127;
        const float g = __int_as_float((127 - e) << 23);    // exact 2^-e
        Ev = (sum * g) * X;

        Eb[pb ^ 1][lane] = Ev;
        Sb[pb ^ 1][lane] = sc;
        __syncwarp();

        // ---------- off-chain: offset + EXACT first-index argmax + store ----------
        O = fmaf((float)e, LN2, O + fv0);
        unsigned eq = 0;
        #pragma unroll
        for (int h = 0; h < T; h++)
            if (vv[h] == vmax) eq |= (1u << h);
        __stcs(pout, (float)(__ffs(eq) - 1));
        pout += BT;
    }

    if (len < S) {
        // Frozen scores: Sb[len&1] holds final sc. One more argmax = tail ptr.
        const float4* s4 = (const float4*)Sb[len & 1];
        float vv[T];
        #pragma unroll
        for (int k = 0; k < 8; k++) {
            const float4 q = s4[k];
            vv[4 * k]     = q.x + tr[4 * k];
            vv[4 * k + 1] = q.y + tr[4 * k + 1];
            vv[4 * k + 2] = q.z + tr[4 * k + 2];
            vv[4 * k + 3] = q.w + tr[4 * k + 3];
        }
        float mx[16];
        #pragma unroll
        for (int i = 0; i < 16; i++) mx[i] = fmaxf(vv[i], vv[i + 16]);
        #pragma unroll
        for (int off = 8; off; off >>= 1)
            #pragma unroll
            for (int i = 0; i < 8; i++)
                if (i < off) mx[i] = fmaxf(mx[i], mx[i + off]);
        const float vmax = mx[0];
        unsigned eq = 0;
        #pragma unroll
        for (int h = 0; h < T; h++)
            if (vv[h] == vmax) eq |= (1u << h);
        const float pv = (float)(__ffs(eq) - 1);
        #pragma unroll 4
        for (int s = len; s < S; s++) { __stcs(pout, pv); pout += BT; }
    }

    // logZ = O + log( sum_i E_i * exp(tstop_i) )   (E bounded)
    {
        float z = Ev * __expf(tstop);
        #pragma unroll
        for (int o = 16; o; o >>= 1)
            z += __shfl_xor_sync(0xffffffffu, z, o);
        if (lane == 0) out[b] = O + __logf(z);
    }
    // best_score = max(sc + t[STOP,:])
    {
        float v = sc + tstop;
        #pragma unroll
        for (int o = 16; o; o >>= 1)
            v = fmaxf(v, __shfl_xor_sync(0xffffffffu, v, o));
        if (lane == 0) out[B + b] = v;
    }
}

extern "C" void kernel_launch(void* const* d_in, const int* in_sizes, int n_in,
                              void* d_out, int out_size) {
    const float* feats = (const float*)d_in[0];
    const float* mask  = (const float*)d_in[1];
    const float* trans = (const float*)d_in[2];
    crf_kernel<<<B, 32>>>(feats, mask, trans, (float*)d_out);
}

// round 13
// speedup vs baseline: 1.6559x; 1.6559x over previous
#include <cuda_runtime.h>
#include <cstdint>

// CRF forward (logZ) + Viterbi merged into ONE warp per batch. Base = R7
// (best: 380us) + counted loop (binary-searched length) + AMORTIZED
// renormalization: forward runs raw in exp-domain (E' = (W·E) * exp(feat)),
// exact power-of-2 renorm only on ODD steps -> no shfl on the chain on even
// steps, and no fv0 shfl ever. Growth bound: <= ~e^36 between renorms with
// N(0,1) data, far below fp32 overflow.
// out (f32): [0,B) logZ, [B,2B) best_score, [2B, 2B+S*B*T) pointers.

constexpr int S = 1024, B = 1024, T = 32;
#define NEG_INF   (-10000.0f)
#define START_TAG 29
#define STOP_TAG  30

__device__ __forceinline__ void ffma2(unsigned long long& d, unsigned long long a, unsigned long long b) {
    asm("fma.rn.f32x2 %0, %1, %2, %0;" : "+l"(d) : "l"(a), "l"(b));
}
__device__ __forceinline__ unsigned long long fadd2(unsigned long long a, unsigned long long b) {
    unsigned long long r;
    asm("add.rn.f32x2 %0, %1, %2;" : "=l"(r) : "l"(a), "l"(b));
    return r;
}
__device__ __forceinline__ unsigned long long pack2(float lo, float hi) {
    unsigned long long r;
    asm("mov.b64 %0, {%1, %2};" : "=l"(r) : "f"(lo), "f"(hi));
    return r;
}
__device__ __forceinline__ void unpack2(unsigned long long v, float& lo, float& hi) {
    asm("mov.b64 {%0, %1}, %2;" : "=f"(lo), "=f"(hi) : "l"(v));
}

__global__ void __launch_bounds__(32) crf_kernel(
    const float* __restrict__ feats, const float* __restrict__ mask,
    const float* __restrict__ trans, float* __restrict__ out)
{
    __shared__ __align__(16) float Eb[2][T];   // forward exp-state broadcast
    __shared__ __align__(16) float Sb[2][T];   // viterbi score broadcast

    const int lane = threadIdx.x;
    const int b    = blockIdx.x;

    // length = first s with mask[s][b]==0 (mask monotone). One-time search.
    int lo = 0, hi = S;
    #pragma unroll 1
    while (lo < hi) {
        const int mid = (lo + hi) >> 1;
        if (__ldg(mask + (size_t)mid * B + b) != 0.0f) lo = mid + 1; else hi = mid;
    }
    const int len = lo;

    const float L2E = 1.4426950408889634f;
    const float LN2 = 0.6931471805599453f;

    // Per-lane transition row (lane = target tag i). W = exp(t) for forward
    // (forbidden -1e4 entries underflow to exactly 0 == contributing -inf).
    unsigned long long W2[T / 2], T2[T / 2];
    #pragma unroll
    for (int k = 0; k < T / 2; k++) {
        const float t0 = __ldg(trans + lane * T + 2 * k);
        const float t1 = __ldg(trans + lane * T + 2 * k + 1);
        T2[k] = pack2(t0, t1);
        W2[k] = pack2(__expf(t0), __expf(t1));
    }
    const float tstop = __ldg(trans + STOP_TAG * T + lane);

    // State: alpha = log(E) + O (O accumulated only at renorm steps).
    float Ev = (lane == START_TAG) ? 1.0f : 0.0f;
    float sc = (lane == START_TAG) ? 0.0f : NEG_INF;
    float O  = 0.0f;

    Eb[0][lane] = Ev;
    Sb[0][lane] = sc;
    __syncwarp();

    const size_t BT = (size_t)B * T;
    const float* fp = feats + (size_t)b * T + lane;

    // Depth-4 register prefetch ring (R7-proven; lead ~4 steps is ample).
    float fq[4];
    #pragma unroll
    for (int k = 0; k < 4; k++) fq[k] = __ldg(fp + (size_t)k * BT);

    float* pout = out + 2 * B + (size_t)b * T + lane;

    #pragma unroll 4
    for (int s = 0; s < len; s++) {
        const int j  = s & 3;                       // constant per unrolled copy
        const int pb = s & 1;
        const float fv = fq[j];
        const int pfr = (s + 4 < S) ? (s + 4) : (S - 1);
        fq[j] = __ldg(fp + (size_t)pfr * BT);

        // X = exp(feat) raw (no shfl; feats absorbed into E's magnitude).
        float X;
        asm("ex2.approx.ftz.f32 %0, %1;" : "=f"(X) : "f"(fv * L2E));

        // ---------- Viterbi chain ----------
        const ulonglong2* s2 = (const ulonglong2*)Sb[pb];
        float vv[T];
        #pragma unroll
        for (int k = 0; k < 8; k++) {
            const ulonglong2 q = s2[k];
            float x0, x1, y0, y1;
            unpack2(fadd2(q.x, T2[2 * k]),     x0, x1);
            unpack2(fadd2(q.y, T2[2 * k + 1]), y0, y1);
            vv[4 * k]     = x0; vv[4 * k + 1] = x1;
            vv[4 * k + 2] = y0; vv[4 * k + 3] = y1;
        }
        float mx[16];
        #pragma unroll
        for (int i = 0; i < 16; i++) mx[i] = fmaxf(vv[i], vv[i + 16]);
        #pragma unroll
        for (int off = 8; off; off >>= 1)
            #pragma unroll
            for (int i = 0; i < 8; i++)
                if (i < off) mx[i] = fmaxf(mx[i], mx[i + off]);
        const float vmax = mx[0];
        sc = vmax + fv;                             // exact update

        // ---------- Forward chain ----------
        const ulonglong2* e2 = (const ulonglong2*)Eb[pb];
        unsigned long long a0 = 0ull, a1 = 0ull, a2 = 0ull, a3 = 0ull;
        #pragma unroll
        for (int k = 0; k < 4; k++) {
            const ulonglong2 qa = e2[2 * k];
            const ulonglong2 qb = e2[2 * k + 1];
            ffma2(a0, qa.x, W2[4 * k]);
            ffma2(a1, qa.y, W2[4 * k + 1]);
            ffma2(a2, qb.x, W2[4 * k + 2]);
            ffma2(a3, qb.y, W2[4 * k + 3]);
        }
        const unsigned long long sAB = fadd2(fadd2(a0, a1), fadd2(a2, a3));
        float sl, sh; unpack2(sAB, sl, sh);
        const float sum = sl + sh;

        if (pb) {
            // Odd step: exact power-of-2 renorm off lane0's sum exponent.
            const int s0b = __shfl_sync(0xffffffffu, __float_as_int(sum), 0);
            const int e   = (s0b >> 23) - 127;
            const float g = __int_as_float((127 - e) << 23);   // exact 2^-e
            Ev = (sum * g) * X;
            O = fmaf((float)e, LN2, O);             // off-chain (used at end only)
        } else {
            Ev = sum * X;                           // no cross-lane traffic
        }

        Eb[pb ^ 1][lane] = Ev;
        Sb[pb ^ 1][lane] = sc;
        __syncwarp();

        // ---------- off-chain: EXACT first-index argmax + pointer store ----------
        unsigned eq = 0;
        #pragma unroll
        for (int h = 0; h < T; h++)
            if (vv[h] == vmax) eq |= (1u << h);
        __stcs(pout, (float)(__ffs(eq) - 1));
        pout += BT;
    }

    if (len < S) {
        // Frozen scores: Sb[len&1] holds final sc. One more argmax = tail ptr.
        const ulonglong2* s2 = (const ulonglong2*)Sb[len & 1];
        float vv[T];
        #pragma unroll
        for (int k = 0; k < 8; k++) {
            const ulonglong2 q = s2[k];
            float x0, x1, y0, y1;
            unpack2(fadd2(q.x, T2[2 * k]),     x0, x1);
            unpack2(fadd2(q.y, T2[2 * k + 1]), y0, y1);
            vv[4 * k]     = x0; vv[4 * k + 1] = x1;
            vv[4 * k + 2] = y0; vv[4 * k + 3] = y1;
        }
        float mx[16];
        #pragma unroll
        for (int i = 0; i < 16; i++) mx[i] = fmaxf(vv[i], vv[i + 16]);
        #pragma unroll
        for (int off = 8; off; off >>= 1)
            #pragma unroll
            for (int i = 0; i < 8; i++)
                if (i < off) mx[i] = fmaxf(mx[i], mx[i + off]);
        const float vmax = mx[0];
        unsigned eq = 0;
        #pragma unroll
        for (int h = 0; h < T; h++)
            if (vv[h] == vmax) eq |= (1u << h);
        const float pv = (float)(__ffs(eq) - 1);
        #pragma unroll 4
        for (int s = len; s < S; s++) { __stcs(pout, pv); pout += BT; }
    }

    // logZ = O + log( sum_i E_i * exp(tstop_i) )   (E bounded by ~e^36)
    {
        float z = Ev * __expf(tstop);
        #pragma unroll
        for (int o = 16; o; o >>= 1)
            z += __shfl_xor_sync(0xffffffffu, z, o);
        if (lane == 0) out[b] = O + __logf(z);
    }
    // best_score = max(sc + t[STOP,:])
    {
        float v = sc + tstop;
        #pragma unroll
        for (int o = 16; o; o >>= 1)
            v = fmaxf(v, __shfl_xor_sync(0xffffffffu, v, o));
        if (lane == 0) out[B + b] = v;
    }
}

extern "C" void kernel_launch(void* const* d_in, const int* in_sizes, int n_in,
                              void* d_out, int out_size) {
    const float* feats = (const float*)d_in[0];
    const float* mask  = (const float*)d_in[1];
    const float* trans = (const float*)d_in[2];
    crf_kernel<<<B, 32>>>(feats, mask, trans, (float*)d_out);
}

// round 14
// speedup vs baseline: 1.6565x; 1.0004x over previous
#include <cuda_runtime.h>
#include <cstdint>

// CRF forward (logZ) + Viterbi merged into ONE warp per batch. Base = R7
// (best: 380us) + counted loop (binary-searched length) + AMORTIZED
// renormalization: forward runs raw in exp-domain (E' = (W·E) * exp(feat)),
// exact power-of-2 renorm only on ODD steps -> no shfl on the chain on even
// steps, and no fv0 shfl ever. Growth bound: <= ~e^36 between renorms with
// N(0,1) data, far below fp32 overflow.
// out (f32): [0,B) logZ, [B,2B) best_score, [2B, 2B+S*B*T) pointers.

constexpr int S = 1024, B = 1024, T = 32;
#define NEG_INF   (-10000.0f)
#define START_TAG 29
#define STOP_TAG  30

__device__ __forceinline__ void ffma2(unsigned long long& d, unsigned long long a, unsigned long long b) {
    asm("fma.rn.f32x2 %0, %1, %2, %0;" : "+l"(d) : "l"(a), "l"(b));
}
__device__ __forceinline__ unsigned long long fadd2(unsigned long long a, unsigned long long b) {
    unsigned long long r;
    asm("add.rn.f32x2 %0, %1, %2;" : "=l"(r) : "l"(a), "l"(b));
    return r;
}
__device__ __forceinline__ unsigned long long pack2(float lo, float hi) {
    unsigned long long r;
    asm("mov.b64 %0, {%1, %2};" : "=l"(r) : "f"(lo), "f"(hi));
    return r;
}
__device__ __forceinline__ void unpack2(unsigned long long v, float& lo, float& hi) {
    asm("mov.b64 {%0, %1}, %2;" : "=f"(lo), "=f"(hi) : "l"(v));
}

__global__ void __launch_bounds__(32) crf_kernel(
    const float* __restrict__ feats, const float* __restrict__ mask,
    const float* __restrict__ trans, float* __restrict__ out)
{
    __shared__ __align__(16) float Eb[2][T];   // forward exp-state broadcast
    __shared__ __align__(16) float Sb[2][T];   // viterbi score broadcast

    const int lane = threadIdx.x;
    const int b    = blockIdx.x;

    // length = first s with mask[s][b]==0 (mask monotone). One-time search.
    int lo = 0, hi = S;
    #pragma unroll 1
    while (lo < hi) {
        const int mid = (lo + hi) >> 1;
        if (__ldg(mask + (size_t)mid * B + b) != 0.0f) lo = mid + 1; else hi = mid;
    }
    const int len = lo;

    const float L2E = 1.4426950408889634f;
    const float LN2 = 0.6931471805599453f;

    // Per-lane transition row (lane = target tag i). W = exp(t) for forward
    // (forbidden -1e4 entries underflow to exactly 0 == contributing -inf).
    unsigned long long W2[T / 2], T2[T / 2];
    #pragma unroll
    for (int k = 0; k < T / 2; k++) {
        const float t0 = __ldg(trans + lane * T + 2 * k);
        const float t1 = __ldg(trans + lane * T + 2 * k + 1);
        T2[k] = pack2(t0, t1);
        W2[k] = pack2(__expf(t0), __expf(t1));
    }
    const float tstop = __ldg(trans + STOP_TAG * T + lane);

    // State: alpha = log(E) + O (O accumulated only at renorm steps).
    float Ev = (lane == START_TAG) ? 1.0f : 0.0f;
    float sc = (lane == START_TAG) ? 0.0f : NEG_INF;
    float O  = 0.0f;

    Eb[0][lane] = Ev;
    Sb[0][lane] = sc;
    __syncwarp();

    const size_t BT = (size_t)B * T;
    const float* fp = feats + (size_t)b * T + lane;

    // Depth-4 register prefetch ring (R7-proven; lead ~4 steps is ample).
    float fq[4];
    #pragma unroll
    for (int k = 0; k < 4; k++) fq[k] = __ldg(fp + (size_t)k * BT);

    float* pout = out + 2 * B + (size_t)b * T + lane;

    #pragma unroll 4
    for (int s = 0; s < len; s++) {
        const int j  = s & 3;                       // constant per unrolled copy
        const int pb = s & 1;
        const float fv = fq[j];
        const int pfr = (s + 4 < S) ? (s + 4) : (S - 1);
        fq[j] = __ldg(fp + (size_t)pfr * BT);

        // X = exp(feat) raw (no shfl; feats absorbed into E's magnitude).
        float X;
        asm("ex2.approx.ftz.f32 %0, %1;" : "=f"(X) : "f"(fv * L2E));

        // ---------- Viterbi chain ----------
        const ulonglong2* s2 = (const ulonglong2*)Sb[pb];
        float vv[T];
        #pragma unroll
        for (int k = 0; k < 8; k++) {
            const ulonglong2 q = s2[k];
            float x0, x1, y0, y1;
            unpack2(fadd2(q.x, T2[2 * k]),     x0, x1);
            unpack2(fadd2(q.y, T2[2 * k + 1]), y0, y1);
            vv[4 * k]     = x0; vv[4 * k + 1] = x1;
            vv[4 * k + 2] = y0; vv[4 * k + 3] = y1;
        }
        float mx[16];
        #pragma unroll
        for (int i = 0; i < 16; i++) mx[i] = fmaxf(vv[i], vv[i + 16]);
        #pragma unroll
        for (int off = 8; off; off >>= 1)
            #pragma unroll
            for (int i = 0; i < 8; i++)
                if (i < off) mx[i] = fmaxf(mx[i], mx[i + off]);
        const float vmax = mx[0];
        sc = vmax + fv;                             // exact update

        // ---------- Forward chain ----------
        const ulonglong2* e2 = (const ulonglong2*)Eb[pb];
        unsigned long long a0 = 0ull, a1 = 0ull, a2 = 0ull, a3 = 0ull;
        #pragma unroll
        for (int k = 0; k < 4; k++) {
            const ulonglong2 qa = e2[2 * k];
            const ulonglong2 qb = e2[2 * k + 1];
            ffma2(a0, qa.x, W2[4 * k]);
            ffma2(a1, qa.y, W2[4 * k + 1]);
            ffma2(a2, qb.x, W2[4 * k + 2]);
            ffma2(a3, qb.y, W2[4 * k + 3]);
        }
        const unsigned long long sAB = fadd2(fadd2(a0, a1), fadd2(a2, a3));
        float sl, sh; unpack2(sAB, sl, sh);
        const float sum = sl + sh;

        if (pb) {
            // Odd step: exact power-of-2 renorm off lane0's sum exponent.
            const int s0b = __shfl_sync(0xffffffffu, __float_as_int(sum), 0);
            const int e   = (s0b >> 23) - 127;
            const float g = __int_as_float((127 - e) << 23);   // exact 2^-e
            Ev = (sum * g) * X;
            O = fmaf((float)e, LN2, O);             // off-chain (used at end only)
        } else {
            Ev = sum * X;                           // no cross-lane traffic
        }

        Eb[pb ^ 1][lane] = Ev;
        Sb[pb ^ 1][lane] = sc;
        __syncwarp();

        // ---------- off-chain: EXACT first-index argmax + pointer store ----------
        unsigned eq = 0;
        #pragma unroll
        for (int h = 0; h < T; h++)
            if (vv[h] == vmax) eq |= (1u << h);
        __stcs(pout, (float)(__ffs(eq) - 1));
        pout += BT;
    }

    if (len < S) {
        // Frozen scores: Sb[len&1] holds final sc. One more argmax = tail ptr.
        const ulonglong2* s2 = (const ulonglong2*)Sb[len & 1];
        float vv[T];
        #pragma unroll
        for (int k = 0; k < 8; k++) {
            const ulonglong2 q = s2[k];
            float x0, x1, y0, y1;
            unpack2(fadd2(q.x, T2[2 * k]),     x0, x1);
            unpack2(fadd2(q.y, T2[2 * k + 1]), y0, y1);
            vv[4 * k]     = x0; vv[4 * k + 1] = x1;
            vv[4 * k + 2] = y0; vv[4 * k + 3] = y1;
        }
        float mx[16];
        #pragma unroll
        for (int i = 0; i < 16; i++) mx[i] = fmaxf(vv[i], vv[i + 16]);
        #pragma unroll
        for (int off = 8; off; off >>= 1)
            #pragma unroll
            for (int i = 0; i < 8; i++)
                if (i < off) mx[i] = fmaxf(mx[i], mx[i + off]);
        const float vmax = mx[0];
        unsigned eq = 0;
        #pragma unroll
        for (int h = 0; h < T; h++)
            if (vv[h] == vmax) eq |= (1u << h);
        const float pv = (float)(__ffs(eq) - 1);
        #pragma unroll 4
        for (int s = len; s < S; s++) { __stcs(pout, pv); pout += BT; }
    }

    // logZ = O + log( sum_i E_i * exp(tstop_i) )   (E bounded by ~e^36)
    {
        float z = Ev * __expf(tstop);
        #pragma unroll
        for (int o = 16; o; o >>= 1)
            z += __shfl_xor_sync(0xffffffffu, z, o);
        if (lane == 0) out[b] = O + __logf(z);
    }
    // best_score = max(sc + t[STOP,:])
    {
        float v = sc + tstop;
        #pragma unroll
        for (int o = 16; o; o >>= 1)
            v = fmaxf(v, __shfl_xor_sync(0xffffffffu, v, o));
        if (lane == 0) out[B + b] = v;
    }
}

extern "C" void kernel_launch(void* const* d_in, const int* in_sizes, int n_in,
                              void* d_out, int out_size) {
    const float* feats = (const float*)d_in[0];
    const float* mask  = (const float*)d_in[1];
    const float* trans = (const float*)d_in[2];
    crf_kernel<<<B, 32>>>(feats, mask, trans, (float*)d_out);
}